// round 7
// baseline (speedup 1.0000x reference)
#include <cuda_runtime.h>

#define NV 50000
#define GD 10
#define GH 162
#define GW 162
#define NPART 240

// ---------------- device scratch (no allocations allowed) ----------------
__device__ int    g_grid[2 * GD * GH * GW];              // padded hash grid
__device__ int    g_nbr[27 * NV];                        // rulebook [k][n]
__device__ float4 g_phi[(NV + 1) * 64];                  // expanded features; pad row = phi(0)
__device__ __align__(16) float g_wc[27 * 256 * 128];     // combined weights [k][4Cin][Cout]
__device__ __align__(16) float g_raw[NV * 128];          // pre-BN conv output
__device__ float  g_part[NPART * 2 * 128];               // BN partial sums
__device__ float  g_mu[128];
__device__ float  g_istd[128];

// ---------------- small utility kernels ----------------
__global__ void k_zero4(float4* p, long n4) {
    long i = (long)blockIdx.x * blockDim.x + threadIdx.x;
    if (i < n4) p[i] = make_float4(0.f, 0.f, 0.f, 0.f);
}

__global__ void k_initgrid() {
    int i = blockIdx.x * blockDim.x + threadIdx.x;
    if (i < 2 * GD * GH * GW) g_grid[i] = NV;   // sentinel = NV (pad row)
}

__global__ void k_scatgrid(const int* __restrict__ coors) {
    int n = blockIdx.x * blockDim.x + threadIdx.x;
    if (n >= NV) return;
    int b = coors[4 * n], z = coors[4 * n + 1], y = coors[4 * n + 2], x = coors[4 * n + 3];
    g_grid[((b * GD + z + 1) * GH + y + 1) * GW + x + 1] = n;
}

__global__ void k_nbr(const int* __restrict__ coors) {
    int n = blockIdx.x * blockDim.x + threadIdx.x;
    if (n >= NV) return;
    int b = coors[4 * n], z = coors[4 * n + 1] + 1, y = coors[4 * n + 2] + 1, x = coors[4 * n + 3] + 1;
    int k = 0;
#pragma unroll
    for (int dz = -1; dz <= 1; dz++)
#pragma unroll
        for (int dy = -1; dy <= 1; dy++)
#pragma unroll
            for (int dx = -1; dx <= 1; dx++) {
                g_nbr[k * NV + n] = g_grid[((b * GD + z + dz) * GH + y + dy) * GW + x + dx];
                k++;
            }
}

// phi(x) = (silu(x), exp(-(x+1)^2), exp(-x^2), exp(-(x-1)^2))   [centers -1,0,1, inv_h=1]
__device__ __forceinline__ float4 phi_of(float x) {
    float s  = x / (1.f + expf(-x));
    float b0 = expf(-(x + 1.f) * (x + 1.f));
    float b1 = expf(-x * x);
    float b2 = expf(-(x - 1.f) * (x - 1.f));
    return make_float4(s, b0, b1, b2);
}

// layer-1 phi from external voxel features; pad row n==NV gets phi(0)
__global__ void k_phi_in(const float* __restrict__ ext) {
    int t = blockIdx.x * blockDim.x + threadIdx.x;
    if (t >= (NV + 1) * 16) return;
    float x = (t < NV * 16) ? ext[t] : 0.f;
    g_phi[t] = phi_of(x);
}

// fused BN(train stats) + ReLU + phi expansion for intermediate layers
template <int COUT>
__global__ void k_bnphi(const float* __restrict__ gm, const float* __restrict__ bt) {
    long t = (long)blockIdx.x * 256 + threadIdx.x;
    if (t >= (long)(NV + 1) * COUT) return;
    float x = 0.f;
    if (t < (long)NV * COUT) {
        int col = (int)(t % COUT);
        float v = (g_raw[t] - g_mu[col]) * g_istd[col] * gm[col] + bt[col];
        x = fmaxf(v, 0.f);
    }
    g_phi[t] = phi_of(x);
}

// fused BN + ReLU + dense scatter for the final layer: out[b, c*8+z, y, x]
__global__ void k_bnscat(const int* __restrict__ coors,
                         const float* __restrict__ gm, const float* __restrict__ bt,
                         float* __restrict__ out) {
    long t = (long)blockIdx.x * 256 + threadIdx.x;
    if (t >= (long)NV * 128) return;
    int n = (int)(t >> 7);
    int c = (int)(t & 127);
    float v = (g_raw[t] - g_mu[c]) * g_istd[c] * gm[c] + bt[c];
    v = fmaxf(v, 0.f);
    int b = coors[4 * n], z = coors[4 * n + 1], y = coors[4 * n + 2], x = coors[4 * n + 3];
    long oi = (((long)(b * 1024 + c * 8 + z)) * 160 + y) * 160 + x;
    out[oi] = v;
}

// Combined weight: Wc[k][c*4+0][o]=wb[k,c,o];  Wc[k][c*4+1+g][o]=ws[k,c,g,o]
template <int CIN, int COUT>
__global__ void k_wc(const float* __restrict__ wb, const float* __restrict__ ws) {
    int t = blockIdx.x * blockDim.x + threadIdx.x;
    if (t >= 27 * 4 * CIN * COUT) return;
    int o = t % COUT;
    int r = t / COUT;
    int j = r % (4 * CIN);
    int k = r / (4 * CIN);
    int c = j >> 2, jj = j & 3;
    g_wc[t] = (jj == 0) ? wb[(k * CIN + c) * COUT + o]
                        : ws[((k * CIN + c) * 3 + (jj - 1)) * COUT + o];
}

// ---------------- gather-GEMM with packed f32x2 FMA ----------------
__device__ __forceinline__ unsigned long long ffma2(unsigned long long a,
                                                    unsigned long long b,
                                                    unsigned long long c) {
    unsigned long long d;
    asm("fma.rn.f32x2 %0, %1, %2, %3;" : "=l"(d) : "l"(a), "l"(b), "l"(c));
    return d;
}

// out[m, nofs+o] = sum_k sum_j phi[nbr[k][m]][j] * Wc[k][j][nofs+o]
// CTA tile: TM voxels x COUT_T cols (nofs = blockIdx.y * COUT_T for N-split),
// 256 threads; each thread 8 voxels (4 f32x2 M-pairs) x TN cols. All configs
// TN<=4 -> acc<=32 regs -> 3 CTAs/SM (regs cap 85), removing the wave tail
// that register-limited occupancy imposed on the big layers.
template <int CIN, int COUT, int COUT_T, int TM, int TN>
__global__ __launch_bounds__(256, 3) void k_gemm() {
    constexpr int KD  = 4 * CIN;      // reduction length per tap
    constexpr int KC  = 32;           // k-chunk
    constexpr int TNG = COUT_T / TN;  // thread groups along N
    constexpr int TPR = 256 / TM;     // threads cooperating per A row
    constexpr int JW  = KC / TPR;     // floats gathered per thread
    static_assert((256 / TNG) * 8 == TM, "tiling");
    static_assert(JW % 4 == 0, "vec");

    __shared__ __align__(16) float As[KC][TM];
    __shared__ __align__(16) float Ws[KC][COUT_T];
    __shared__ int sIdx[TM];

    int tid  = threadIdx.x;
    int tx   = tid % TNG;
    int ty   = tid / TNG;
    int row0 = ty * 8;
    int m0   = blockIdx.x * TM;
    int nofs = blockIdx.y * COUT_T;
    int arow = tid / TPR;
    int aj0  = (tid % TPR) * JW;

    unsigned long long acc[4][TN];
#pragma unroll
    for (int p = 0; p < 4; p++)
#pragma unroll
        for (int i = 0; i < TN; i++) acc[p][i] = 0ull;

    for (int k = 0; k < 27; k++) {
        __syncthreads();
        if (TM == 256 || tid < TM) {
            int m = m0 + tid;
            sIdx[tid] = (m < NV) ? g_nbr[k * NV + m] : NV;   // NV -> phi(0) pad row
        }
        __syncthreads();
        const float*  wck  = g_wc + (size_t)k * KD * COUT + nofs;
        const float4* prow = g_phi + (size_t)sIdx[arow] * CIN;

        for (int jc = 0; jc < KD; jc += KC) {
            // gather A chunk [KC x TM] (store transposed: j-major, m contiguous)
#pragma unroll
            for (int q = 0; q < JW / 4; q++) {
                float4 v = prow[((jc + aj0) >> 2) + q];
                As[aj0 + q * 4 + 0][arow] = v.x;
                As[aj0 + q * 4 + 1][arow] = v.y;
                As[aj0 + q * 4 + 2][arow] = v.z;
                As[aj0 + q * 4 + 3][arow] = v.w;
            }
            // load W chunk [KC x COUT_T] (row stride COUT in gmem), coalesced
#pragma unroll 4
            for (int q = tid; q < KC * COUT_T / 4; q += 256) {
                int wr = q / (COUT_T / 4);
                int wc4 = q % (COUT_T / 4);
                ((float4*)Ws)[q] = *(const float4*)(wck + (size_t)(jc + wr) * COUT + wc4 * 4);
            }
            __syncthreads();

#pragma unroll
            for (int j = 0; j < KC; j++) {
                // 8 voxels of A as 4 f32x2 pairs (warp-broadcast LDS.128, conflict-free)
                ulonglong2 pa = *(const ulonglong2*)&As[j][row0];
                ulonglong2 pb = *(const ulonglong2*)&As[j][row0 + 4];
#pragma unroll
                for (int i = 0; i < TN; i++) {
                    unsigned int bi = __float_as_uint(Ws[j][tx + i * TNG]);
                    unsigned long long b2;
                    asm("mov.b64 %0, {%1, %1};" : "=l"(b2) : "r"(bi));
                    acc[0][i] = ffma2(pa.x, b2, acc[0][i]);
                    acc[1][i] = ffma2(pa.y, b2, acc[1][i]);
                    acc[2][i] = ffma2(pb.x, b2, acc[2][i]);
                    acc[3][i] = ffma2(pb.y, b2, acc[3][i]);
                }
            }
            __syncthreads();
        }
    }

    // epilogue: unpack f32x2 pairs, store pre-BN output
#pragma unroll
    for (int p = 0; p < 4; p++) {
        int r = m0 + row0 + 2 * p;
#pragma unroll
        for (int i = 0; i < TN; i++) {
            unsigned int lo, hi;
            asm("mov.b64 {%0, %1}, %2;" : "=r"(lo), "=r"(hi) : "l"(acc[p][i]));
            int col = nofs + tx + i * TNG;
            if (r < NV)     g_raw[(size_t)r * COUT + col]       = __uint_as_float(lo);
            if (r + 1 < NV) g_raw[(size_t)(r + 1) * COUT + col] = __uint_as_float(hi);
        }
    }
}

// ---------------- BatchNorm statistics (deterministic tree reduction) ----------------
template <int COUT>
__global__ void k_stats1() {
    constexpr int RP = 256 / COUT;
    int tid = threadIdx.x;
    int col = tid % COUT, rg = tid / COUT;
    float s = 0.f, q = 0.f;
    for (int r = blockIdx.x * RP + rg; r < NV; r += NPART * RP) {
        float v = g_raw[(size_t)r * COUT + col];
        s += v;
        q += v * v;
    }
    __shared__ float sh[256], sh2[256];
    sh[tid] = s; sh2[tid] = q;
    __syncthreads();
    if (rg == 0) {
#pragma unroll
        for (int g2 = 1; g2 < RP; g2++) { s += sh[g2 * COUT + col]; q += sh2[g2 * COUT + col]; }
        g_part[blockIdx.x * 2 * COUT + col]        = s;
        g_part[blockIdx.x * 2 * COUT + COUT + col] = q;
    }
}

template <int COUT>
__global__ void k_stats2() {
    int col = threadIdx.x;
    if (col >= COUT) return;
    double s = 0.0, q = 0.0;
    for (int b = 0; b < NPART; b++) {
        s += (double)g_part[b * 2 * COUT + col];
        q += (double)g_part[b * 2 * COUT + COUT + col];
    }
    double mu  = s / (double)NV;
    double var = q / (double)NV - mu * mu;
    g_mu[col]   = (float)mu;
    g_istd[col] = (float)(1.0 / sqrt(var + 1e-3));
}

// ---------------- host orchestration ----------------
template <int CIN, int COUT, int COUT_T, int TM, int TN>
static void run_gemm_block(const float* wb, const float* ws) {
    k_wc<CIN, COUT><<<(27 * 4 * CIN * COUT + 255) / 256, 256>>>(wb, ws);
    dim3 grid((NV + TM - 1) / TM, COUT / COUT_T);
    k_gemm<CIN, COUT, COUT_T, TM, TN><<<grid, 256>>>();
    k_stats1<COUT><<<NPART, 256>>>();
    k_stats2<COUT><<<1, 128>>>();
}

extern "C" void kernel_launch(void* const* d_in, const int* in_sizes, int n_in,
                              void* d_out, int out_size) {
    const float* vf    = (const float*)d_in[0];
    const int*   coors = (const int*)d_in[1];
    // d_in[2] = batch_size (compile-time B=2)
    const float *wb[5], *ws[5], *gm[5], *bt[5];
    for (int i = 0; i < 5; i++) {
        wb[i] = (const float*)d_in[3 + 4 * i];
        ws[i] = (const float*)d_in[4 + 4 * i];
        gm[i] = (const float*)d_in[5 + 4 * i];
        bt[i] = (const float*)d_in[6 + 4 * i];
    }

    // rulebook + layer-1 phi
    k_initgrid<<<(2 * GD * GH * GW + 255) / 256, 256>>>();
    k_scatgrid<<<(NV + 255) / 256, 256>>>(coors);
    k_nbr<<<(NV + 255) / 256, 256>>>(coors);
    k_phi_in<<<(((NV + 1) * 16) + 255) / 256, 256>>>(vf);

    // L1: 16 -> 16
    run_gemm_block<16, 16, 16, 256, 2>(wb[0], ws[0]);
    k_bnphi<16><<<(int)((((long)(NV + 1) * 16) + 255) / 256), 256>>>(gm[0], bt[0]);

    // L2: 16 -> 32
    run_gemm_block<16, 32, 32, 256, 4>(wb[1], ws[1]);
    k_bnphi<32><<<(int)((((long)(NV + 1) * 32) + 255) / 256), 256>>>(gm[1], bt[1]);

    // L3: 32 -> 64
    run_gemm_block<32, 64, 64, 128, 4>(wb[2], ws[2]);
    k_bnphi<64><<<(int)((((long)(NV + 1) * 64) + 255) / 256), 256>>>(gm[2], bt[2]);

    // L4: 64 -> 64
    run_gemm_block<64, 64, 64, 128, 4>(wb[3], ws[3]);
    k_bnphi<64><<<(int)((((long)(NV + 1) * 64) + 255) / 256), 256>>>(gm[3], bt[3]);

    // L5: 64 -> 128, N-split into two 64-col halves (occ 3, finer quantization)
    run_gemm_block<64, 128, 64, 128, 4>(wb[4], ws[4]);

    // zero dense output (poisoned by harness), then fused BN+ReLU+scatter
    long n4 = (long)out_size / 4;
    k_zero4<<<(int)((n4 + 255) / 256), 256>>>((float4*)d_out, n4);
    k_bnscat<<<(int)((((long)NV * 128) + 255) / 256), 256>>>(coors, gm[4], bt[4], (float*)d_out);
}